// round 10
// baseline (speedup 1.0000x reference)
#include <cuda_runtime.h>
#include <cstdint>

// Problem constants
#define B_TOT   256
#define IN_CAPS 3200
#define NJ      8
#define NM      16
#define NN      8
#define JM      (NJ * NM)          // 128

// Tiling
#define IC      32                 // input caps per chunk
#define NCHUNK  (IN_CAPS / IC)     // 100
#define BPC     64                 // batch elems per CTA (16 warps x 4 lane-b)
#define NBB     (B_TOT / BPC)      // 4
#define WSTRIDE 132                // padded floats per (i,j) row in SMEM
#define XS_FLOATS (BPC * IC * NN)  // 16384 floats = 64KB x tile
#define SMEM_BYTES (XS_FLOATS * 4 + IC * NJ * WSTRIDE * 4)   // 200704 B

// Scratch (static device arrays; no runtime allocation)
// logits packed [bgroup(64)][i(3200)][j(8)][b4(4)] -> 1-wavefront store/load
__device__ float g_logits[(size_t)(B_TOT / 4) * IN_CAPS * NJ * 4];   // 26.2 MB
__device__ float g_part[(size_t)NCHUNK * B_TOT * JM];                // 13.1 MB
__device__ float g_v[B_TOT * JM];                                    // v between passes

typedef unsigned long long ull;

__device__ __forceinline__ ull pk2(float a, float b) {
    ull r; asm("mov.b64 %0, {%1, %2};" : "=l"(r) : "f"(a), "f"(b)); return r;
}
__device__ __forceinline__ void upk2(float& a, float& b, ull x) {
    asm("mov.b64 {%0, %1}, %2;" : "=f"(a), "=f"(b) : "l"(x));
}
// packed f32x2 fma: d = a*b + d
__device__ __forceinline__ void fma2(ull& d, ull a, ull b) {
    asm("fma.rn.f32x2 %0, %1, %2, %0;" : "+l"(d) : "l"(a), "l"(b));
}
// packed f32x2 mul: d = a*b
__device__ __forceinline__ void mul2(ull& d, ull a, ull b) {
    asm("mul.rn.f32x2 %0, %1, %2;" : "=l"(d) : "l"(a), "l"(b));
}

// Trivial warm-up so ncu (-s 5 -c 1) lands on routing_pass<2> at launch idx 5.
__global__ void warmup_probe() {
    if (threadIdx.x < JM) g_v[threadIdx.x] = 0.f;   // overwritten before first read
}

// Lane layout: lane = bsub*8 + j (bsub = batch sub-idx 0..3, j = out-cap 0..7).
// Each lane owns ALL 16 m of one (b, j): u/s/v = 8 f32x2 pairs, dot over m is
// fully in-register (no closure shfl). Softmax over j = shfl.xor 1,2,4 — the 4
// bsub groups do their 4 b's concurrently, so 3 shfl + 1 exp + 1 div per
// warp-il covers everything (was 20 shfl + 4 exp + 4 div).
// W LDS: per LDS.128 the 8 distinct j-segments (stride 528 B = 4 banks mod 32)
// tile all 32 banks; 4-way bsub duplicates are broadcast-dedup'd -> 1 cyc/wf.
// MODE 0: uniform c = 1/8 — accumulate u into s directly, scale at end.
// MODE 1: a = u.v0; logits = a (stored packed); c = softmax_j(a).
// MODE 2: a = u.v1; logits = stored + a; c = softmax_j(logits).
template <int MODE>
__global__ void __launch_bounds__(512, 1) routing_pass(
    const float* __restrict__ x, const float* __restrict__ W)
{
    extern __shared__ float smem_f[];
    float* Xs = smem_f;                  // [BPC][IC][NN]  (CTA-local batch idx)
    float* Ws = smem_f + XS_FLOATS;      // [IC][NJ][WSTRIDE]

    const int chunk = blockIdx.x;
    const int bblk  = blockIdx.y;
    const int tid   = threadIdx.x;
    const int i0    = chunk * IC;

    // Stage W[i0:i0+IC] into SMEM (padded rows).
    {
        const float4* Wg = (const float4*)(W + (size_t)i0 * NJ * NN * NM);
        #pragma unroll 4
        for (int q = tid; q < IC * NJ * 32; q += 512) {
            float4 w = Wg[q];
            int ij = q >> 5, r = q & 31;
            *(float4*)&Ws[ij * WSTRIDE + r * 4] = w;
        }
    }
    // Stage x tile [BPC][IC][NN] into SMEM (coalesced; 8 float4 per thread).
    {
        #pragma unroll
        for (int q = tid; q < BPC * IC * 2; q += 512) {
            int b = q >> 6;              // 64 float4 per batch elem
            int r = q & 63;
            *(float4*)&Xs[b * (IC * NN) + r * 4] =
                *(const float4*)(x + ((size_t)(bblk * BPC + b) * IN_CAPS + i0) * NN + r * 4);
        }
    }
    __syncthreads();

    const int lane  = tid & 31;
    const int warp  = tid >> 5;
    const int bsub  = lane >> 3;          // batch sub-index within warp
    const int j     = lane & 7;           // out-capsule
    const int b_cta = warp * 4 + bsub;    // CTA-local batch idx
    const int b     = bblk * BPC + b_cta;
    const int bgroup = (bblk * BPC + warp * 4) >> 2;   // logits group (per warp)

    // v for this (b, j): 8 m-pairs in regs (MODE>0)
    ull v2[8];
    if (MODE) {
        const float4* vp = (const float4*)(g_v + (size_t)b * JM + j * NM);
        #pragma unroll
        for (int q = 0; q < 4; q++) {
            float4 vv = vp[q];
            v2[2 * q]     = pk2(vv.x, vv.y);
            v2[2 * q + 1] = pk2(vv.z, vv.w);
        }
    }

    ull s2[8];
    #pragma unroll
    for (int k = 0; k < 8; k++) s2[k] = 0ull;

    // per-lane packed-logit slot: [i][j][bsub], stride 32 floats per i
    float* lptr = g_logits + ((size_t)bgroup * IN_CAPS + i0) * 32 + j * 4 + bsub;
    const float* xlane = Xs + (size_t)b_cta * (IC * NN);

    #pragma unroll 1
    for (int il = 0; il < IC; il++) {
        // prev logit (MODE 2): 32 distinct contiguous floats = 1 LDG wavefront
        float pl;
        if (MODE == 2) pl = lptr[(size_t)il * 32];

        // x[b, il, :]: 2 LDS.128 (4 distinct addrs x 8-way broadcast)
        const float4* xp = (const float4*)&xlane[il * NN];
        float4 A = xp[0], Bq = xp[1];
        float xn[8] = {A.x, A.y, A.z, A.w, Bq.x, Bq.y, Bq.z, Bq.w};

        const ulonglong2* wrow = (const ulonglong2*)&Ws[(il * NJ + j) * WSTRIDE];

        if (MODE == 0) {
            // c uniform: accumulate u straight into s across n and il
            #pragma unroll
            for (int n = 0; n < 8; n++) {
                ulonglong2 w0 = wrow[n * 4 + 0], w1 = wrow[n * 4 + 1];
                ulonglong2 w2 = wrow[n * 4 + 2], w3 = wrow[n * 4 + 3];
                ull xd = pk2(xn[n], xn[n]);
                fma2(s2[0], w0.x, xd); fma2(s2[1], w0.y, xd);
                fma2(s2[2], w1.x, xd); fma2(s2[3], w1.y, xd);
                fma2(s2[4], w2.x, xd); fma2(s2[5], w2.y, xd);
                fma2(s2[6], w3.x, xd); fma2(s2[7], w3.y, xd);
            }
        } else {
            // u[j][0:16] for this (b, i): 32 LDS.128 + 64 fma2
            ull u2[8];
            {
                ulonglong2 w0 = wrow[0], w1 = wrow[1], w2 = wrow[2], w3 = wrow[3];
                ull xd = pk2(xn[0], xn[0]);
                mul2(u2[0], w0.x, xd); mul2(u2[1], w0.y, xd);
                mul2(u2[2], w1.x, xd); mul2(u2[3], w1.y, xd);
                mul2(u2[4], w2.x, xd); mul2(u2[5], w2.y, xd);
                mul2(u2[6], w3.x, xd); mul2(u2[7], w3.y, xd);
            }
            #pragma unroll
            for (int n = 1; n < 8; n++) {
                ulonglong2 w0 = wrow[n * 4 + 0], w1 = wrow[n * 4 + 1];
                ulonglong2 w2 = wrow[n * 4 + 2], w3 = wrow[n * 4 + 3];
                ull xd = pk2(xn[n], xn[n]);
                fma2(u2[0], w0.x, xd); fma2(u2[1], w0.y, xd);
                fma2(u2[2], w1.x, xd); fma2(u2[3], w1.y, xd);
                fma2(u2[4], w2.x, xd); fma2(u2[5], w2.y, xd);
                fma2(u2[6], w3.x, xd); fma2(u2[7], w3.y, xd);
            }

            // a = v.u — fully lane-local (two parallel chains, then combine)
            ull acc0 = 0ull, acc1 = 0ull;
            fma2(acc0, u2[0], v2[0]); fma2(acc1, u2[1], v2[1]);
            fma2(acc0, u2[2], v2[2]); fma2(acc1, u2[3], v2[3]);
            fma2(acc0, u2[4], v2[4]); fma2(acc1, u2[5], v2[5]);
            fma2(acc0, u2[6], v2[6]); fma2(acc1, u2[7], v2[7]);
            float l0, h0, l1, h1;
            upk2(l0, h0, acc0); upk2(l1, h1, acc1);
            float a = (l0 + h0) + (l1 + h1);

            float logit = a;
            if (MODE == 2) logit += pl;
            if (MODE == 1) lptr[(size_t)il * 32] = a;   // 1 coalesced wavefront

            // softmax over the 8 j-lanes of this bsub group (logits O(0.1))
            float e = __expf(logit);
            float sm = e;
            sm += __shfl_xor_sync(0xffffffffu, sm, 1);
            sm += __shfl_xor_sync(0xffffffffu, sm, 2);
            sm += __shfl_xor_sync(0xffffffffu, sm, 4);
            float c = __fdividef(e, sm);

            ull cd = pk2(c, c);
            #pragma unroll
            for (int k = 0; k < 8; k++) fma2(s2[k], u2[k], cd);
        }
    }

    if (MODE == 0) {
        #pragma unroll
        for (int k = 0; k < 8; k++) {
            float lo, hi; upk2(lo, hi, s2[k]);
            s2[k] = pk2(lo * 0.125f, hi * 0.125f);
        }
    }

    // write s-partials: 4 float4 per lane, distinct (b, j, m) regions
    {
        float* pp = g_part + ((size_t)chunk * B_TOT + b) * JM + j * NM;
        #pragma unroll
        for (int q = 0; q < 4; q++) {
            float a0, a1, a2, a3;
            upk2(a0, a1, s2[2 * q]); upk2(a2, a3, s2[2 * q + 1]);
            *(float4*)(pp + q * 4) = make_float4(a0, a1, a2, a3);
        }
    }
}

// Sum partials over chunks (4 parallel groups of 25, deterministic), squash, write v.
__global__ void __launch_bounds__(512) reduce_squash(float* __restrict__ vout)
{
    const int b = blockIdx.x, t = threadIdx.x;
    const int g = t >> 7, w = t & 127;        // group 0..3, element 0..127
    __shared__ float sh[4][JM];

    const float* p = g_part + ((size_t)(g * 25) * B_TOT + b) * JM + w;
    float a0 = 0.f, a1 = 0.f, a2 = 0.f, a3 = 0.f;
    #pragma unroll
    for (int k = 0; k < 24; k += 4) {
        a0 += p[(size_t)(k + 0) * B_TOT * JM];
        a1 += p[(size_t)(k + 1) * B_TOT * JM];
        a2 += p[(size_t)(k + 2) * B_TOT * JM];
        a3 += p[(size_t)(k + 3) * B_TOT * JM];
    }
    a0 += p[(size_t)24 * B_TOT * JM];
    sh[g][w] = (a0 + a1) + (a2 + a3);
    __syncthreads();

    if (t < JM) {
        float tot = ((sh[0][t] + sh[1][t]) + (sh[2][t] + sh[3][t]));
        const int j = t >> 4;
        float sq = 0.f;
        #pragma unroll
        for (int m = 0; m < NM; m++) {
            int e = j * NM + m;
            float z = ((sh[0][e] + sh[1][e]) + (sh[2][e] + sh[3][e]));
            sq += z * z;
        }
        float f = sq / ((1.0f + sq) * sqrtf(sq));
        vout[b * JM + t] = tot * f;
    }
}

extern "C" void kernel_launch(void* const* d_in, const int* in_sizes, int n_in,
                              void* d_out, int out_size)
{
    const float* x = (const float*)d_in[0];
    const float* W = (const float*)d_in[1];
    // defensive: identify by element count (x: 6,553,600; W: 3,276,800)
    if (n_in >= 2 && in_sizes[0] == IN_CAPS * NJ * NN * NM) {
        W = (const float*)d_in[0];
        x = (const float*)d_in[1];
    }

    cudaFuncSetAttribute(routing_pass<0>, cudaFuncAttributeMaxDynamicSharedMemorySize, SMEM_BYTES);
    cudaFuncSetAttribute(routing_pass<1>, cudaFuncAttributeMaxDynamicSharedMemorySize, SMEM_BYTES);
    cudaFuncSetAttribute(routing_pass<2>, cudaFuncAttributeMaxDynamicSharedMemorySize, SMEM_BYTES);

    float* vbuf = nullptr;
    cudaGetSymbolAddress((void**)&vbuf, g_v);

    dim3 grid(NCHUNK, NBB);

    // launch 0: probe so ncu (-s 5) captures routing_pass<2> at index 5
    warmup_probe<<<1, 128>>>();
    // iteration 0: c uniform -> s0 -> v0
    routing_pass<0><<<grid, 512, SMEM_BYTES>>>(x, W);
    reduce_squash<<<B_TOT, 512>>>(vbuf);
    // iteration 1: logits = a(v0); c = softmax -> s1 -> v1
    routing_pass<1><<<grid, 512, SMEM_BYTES>>>(x, W);
    reduce_squash<<<B_TOT, 512>>>(vbuf);
    // final: logits += a(v1); c = softmax -> s2 -> v2 = output
    routing_pass<2><<<grid, 512, SMEM_BYTES>>>(x, W);
    reduce_squash<<<B_TOT, 512>>>((float*)d_out);
}

// round 12
// speedup vs baseline: 1.7089x; 1.7089x over previous
#include <cuda_runtime.h>
#include <cstdint>

// Problem constants
#define B_TOT   256
#define IN_CAPS 3200
#define NJ      8
#define NM      16
#define NN      8
#define JM      (NJ * NM)          // 128

// Tiling
#define IC      32                 // input caps per chunk
#define NCHUNK  (IN_CAPS / IC)     // 100
#define BPC     64                 // batch elems per CTA (16 warps x 4 b)
#define NBB     (B_TOT / BPC)      // 4
#define WSTRIDE 132                // padded floats per (i,j) row in SMEM
#define XROWS   (IC * NN)          // 256 rows of the transposed x tile
#define XS_FLOATS (XROWS * BPC)    // 16384 floats = 64KB
#define SMEM_BYTES (XS_FLOATS * 4 + IC * NJ * WSTRIDE * 4)   // 200704 B

// Scratch (static device arrays; no runtime allocation)
// logits packed [bgroup(64)][i(3200)][j(8)][b4(4)] -> 1-wavefront store/load
__device__ float g_logits[(size_t)(B_TOT / 4) * IN_CAPS * NJ * 4];   // 26.2 MB
__device__ float g_part[(size_t)NCHUNK * B_TOT * JM];                // 13.1 MB
__device__ float g_v[B_TOT * JM];                                    // v between passes

typedef unsigned long long ull;

__device__ __forceinline__ ull pk2(float a, float b) {
    ull r; asm("mov.b64 %0, {%1, %2};" : "=l"(r) : "f"(a), "f"(b)); return r;
}
__device__ __forceinline__ void upk2(float& a, float& b, ull x) {
    asm("mov.b64 {%0, %1}, %2;" : "=f"(a), "=f"(b) : "l"(x));
}
// packed f32x2 fma: d = a*b + d
__device__ __forceinline__ void fma2(ull& d, ull a, ull b) {
    asm("fma.rn.f32x2 %0, %1, %2, %0;" : "+l"(d) : "l"(a), "l"(b));
}
// packed f32x2 mul: d = a*b
__device__ __forceinline__ void mul2(ull& d, ull a, ull b) {
    asm("mul.rn.f32x2 %0, %1, %2;" : "=l"(d) : "l"(a), "l"(b));
}

// Trivial warm-up so ncu (-s 5 -c 1) lands on routing_pass<2> at launch idx 5.
__global__ void warmup_probe() {
    if (threadIdx.x < JM) g_v[threadIdx.x] = 0.f;   // overwritten before first read
}

// Lane layout (R9, proven): lane = mq*8 + j. Per W LDS.128 all 32 lanes read
// DISTINCT 16B (512B = 4 wavefronts, conflict-free with WSTRIDE=132); 4 b's
// amortize each W read. u/s/v m-packed f32x2 (lane owns 4 m).
// x is re-staged TRANSPOSED+SWIZZLED: Xs2[row=il*8+n][phys_col4=(c4+row)&15]
// holds x[b=c4*4..+4][il][n] as one float4 -> per n a single broadcast LDS.128
// feeds all 4 b's (operand lives 4 regs, not 32).
// MODE 1/2 software-pipeline: s += c_prev*u_prev is applied one il late, so
// the serial shfl/exp/div softmax chain overlaps the next il's FMA block.
template <int MODE>
__global__ void __launch_bounds__(512, 1) routing_pass(
    const float* __restrict__ x, const float* __restrict__ W)
{
    extern __shared__ float smem_f[];
    float* Xs2 = smem_f;                 // [XROWS][64] swizzled
    float* Ws  = smem_f + XS_FLOATS;     // [IC][NJ][WSTRIDE]

    const int chunk = blockIdx.x;
    const int bblk  = blockIdx.y;
    const int tid   = threadIdx.x;
    const int i0    = chunk * IC;

    // Stage W[i0:i0+IC] into SMEM (padded rows).
    {
        const float4* Wg = (const float4*)(W + (size_t)i0 * NJ * NN * NM);
        #pragma unroll 4
        for (int q = tid; q < IC * NJ * 32; q += 512) {
            float4 w = Wg[q];
            int ij = q >> 5, r = q & 31;
            *(float4*)&Ws[ij * WSTRIDE + r * 4] = w;
        }
    }
    // Stage x transposed: row = il*8+n, gather 4 b's per float4, swizzle col.
    {
        const float* xg = x + (size_t)(bblk * BPC) * IN_CAPS * NN + (size_t)i0 * NN;
        #pragma unroll
        for (int q = tid; q < XROWS * 16; q += 512) {
            int row = q & 255;           // il*8 + n
            int c4  = q >> 8;            // b-group 0..15
            const float* xb = xg + (size_t)(c4 * 4) * IN_CAPS * NN + row;
            float4 vr = make_float4(xb[0],
                                    xb[(size_t)IN_CAPS * NN],
                                    xb[(size_t)2 * IN_CAPS * NN],
                                    xb[(size_t)3 * IN_CAPS * NN]);
            *(float4*)&Xs2[row * 64 + (((c4 + row) & 15) << 2)] = vr;
        }
    }
    __syncthreads();

    const int lane = tid & 31;
    const int warp = tid >> 5;
    const int mq   = lane >> 3;           // m-quarter
    const int j    = lane & 7;
    const int bbase = bblk * BPC + warp * 4;
    const int bgroup = bbase >> 2;        // logits group (one per warp)

    // v for the 4 b's (MODE>0): 2 pairs each, m-packed
    ull v2[4][2];
    if (MODE) {
        #pragma unroll
        for (int b = 0; b < 4; b++) {
            float4 vv = *(const float4*)(g_v + (size_t)(bbase + b) * JM + j * NM + mq * 4);
            v2[b][0] = pk2(vv.x, vv.y);
            v2[b][1] = pk2(vv.z, vv.w);
        }
    }

    ull s2[4][2];
    #pragma unroll
    for (int b = 0; b < 4; b++) { s2[b][0] = 0ull; s2[b][1] = 0ull; }

    float* lrow = g_logits + ((size_t)bgroup * IN_CAPS + i0) * 32 + j * 4;

    // u-compute for one il into buffer u[4][2] (n-outer, shared wv + xq per n)
    auto LOAD_U = [&](ull u[4][2], int il) {
        const ulonglong2* wrow =
            (const ulonglong2*)&Ws[(il * NJ + j) * WSTRIDE + mq * 4];
        {
            ulonglong2 wv = wrow[0];
            int row = il * 8;
            float4 xq = *(const float4*)&Xs2[row * 64 + (((warp + row) & 15) << 2)];
            float xb[4] = {xq.x, xq.y, xq.z, xq.w};
            #pragma unroll
            for (int b = 0; b < 4; b++) {
                ull xd = pk2(xb[b], xb[b]);
                mul2(u[b][0], wv.x, xd);
                mul2(u[b][1], wv.y, xd);
            }
        }
        #pragma unroll
        for (int n = 1; n < 8; n++) {
            ulonglong2 wv = wrow[n * 4];
            int row = il * 8 + n;
            float4 xq = *(const float4*)&Xs2[row * 64 + (((warp + row) & 15) << 2)];
            float xb[4] = {xq.x, xq.y, xq.z, xq.w};
            #pragma unroll
            for (int b = 0; b < 4; b++) {
                ull xd = pk2(xb[b], xb[b]);
                fma2(u[b][0], wv.x, xd);
                fma2(u[b][1], wv.y, xd);
            }
        }
    };

    if (MODE == 0) {
        // c uniform: accumulate u straight into s across il; scale at end
        #pragma unroll 2
        for (int il = 0; il < IC; il++) {
            const ulonglong2* wrow =
                (const ulonglong2*)&Ws[(il * NJ + j) * WSTRIDE + mq * 4];
            #pragma unroll
            for (int n = 0; n < 8; n++) {
                ulonglong2 wv = wrow[n * 4];
                int row = il * 8 + n;
                float4 xq = *(const float4*)&Xs2[row * 64 + (((warp + row) & 15) << 2)];
                float xb[4] = {xq.x, xq.y, xq.z, xq.w};
                #pragma unroll
                for (int b = 0; b < 4; b++) {
                    ull xd = pk2(xb[b], xb[b]);
                    fma2(s2[b][0], wv.x, xd);
                    fma2(s2[b][1], wv.y, xd);
                }
            }
        }
        #pragma unroll
        for (int b = 0; b < 4; b++) {
            float lo, hi;
            upk2(lo, hi, s2[b][0]); s2[b][0] = pk2(lo * 0.125f, hi * 0.125f);
            upk2(lo, hi, s2[b][1]); s2[b][1] = pk2(lo * 0.125f, hi * 0.125f);
        }
    } else {
        ull ua[4][2], ub[4][2];
        float cp[4];

        // a -> c for buffer u at iteration il; fills cp
        auto CLOSE = [&](ull u[4][2], int il) {
            float a4[4];
            #pragma unroll
            for (int b = 0; b < 4; b++) {
                ull acc = 0ull;
                fma2(acc, u[b][0], v2[b][0]);
                fma2(acc, u[b][1], v2[b][1]);
                float lo, hi; upk2(lo, hi, acc);
                float a = lo + hi;
                a += __shfl_xor_sync(0xffffffffu, a, 8);
                a += __shfl_xor_sync(0xffffffffu, a, 16);
                a4[b] = a;
            }
            float4 pl4;
            if (MODE == 2) pl4 = *(const float4*)(lrow + (size_t)il * 32);
            if (MODE == 1 && mq == 0)
                *(float4*)(lrow + (size_t)il * 32) =
                    make_float4(a4[0], a4[1], a4[2], a4[3]);
            #pragma unroll
            for (int b = 0; b < 4; b++) {
                float logit = a4[b];
                if (MODE == 2)
                    logit += (b == 0) ? pl4.x : (b == 1) ? pl4.y
                           : (b == 2) ? pl4.z : pl4.w;
                float e = __expf(logit);
                float sm = e;
                sm += __shfl_xor_sync(0xffffffffu, sm, 1);
                sm += __shfl_xor_sync(0xffffffffu, sm, 2);
                sm += __shfl_xor_sync(0xffffffffu, sm, 4);
                cp[b] = __fdividef(e, sm);
            }
        };
        auto APPLY = [&](ull u[4][2]) {
            #pragma unroll
            for (int b = 0; b < 4; b++) {
                ull cd = pk2(cp[b], cp[b]);
                fma2(s2[b][0], u[b][0], cd);
                fma2(s2[b][1], u[b][1], cd);
            }
        };

        // prologue: il = 0 into ua
        LOAD_U(ua, 0);
        CLOSE(ua, 0);
        // steady state: loop covers pairs (1,2)..(29,30); each CLOSE's softmax
        // chain is hidden under the following LOAD_U's FMA block
        #pragma unroll 1
        for (int il = 1; il < IC - 1; il += 2) {
            LOAD_U(ub, il);
            APPLY(ua);          // s += c(il-1) * u(il-1)
            CLOSE(ub, il);
            LOAD_U(ua, il + 1);
            APPLY(ub);          // s += c(il) * u(il)
            CLOSE(ua, il + 1);
        }
        // epilogue: after loop ua = u(30) closed; handle il = 31 and tails
        LOAD_U(ub, IC - 1);
        APPLY(ua);              // s += c(30) * u(30)
        CLOSE(ub, IC - 1);
        APPLY(ub);              // s += c(31) * u(31)
    }

    // write s-partials: one float4 per (lane, b)
    #pragma unroll
    for (int b = 0; b < 4; b++) {
        float a0, a1, a2, a3;
        upk2(a0, a1, s2[b][0]); upk2(a2, a3, s2[b][1]);
        float* pp = g_part + ((size_t)chunk * B_TOT + bbase + b) * JM + j * NM + mq * 4;
        *(float4*)pp = make_float4(a0, a1, a2, a3);
    }
}

// Sum partials over chunks (4 parallel groups of 25, deterministic), squash, write v.
__global__ void __launch_bounds__(512) reduce_squash(float* __restrict__ vout)
{
    const int b = blockIdx.x, t = threadIdx.x;
    const int g = t >> 7, w = t & 127;        // group 0..3, element 0..127
    __shared__ float sh[4][JM];

    const float* p = g_part + ((size_t)(g * 25) * B_TOT + b) * JM + w;
    float a0 = 0.f, a1 = 0.f, a2 = 0.f, a3 = 0.f;
    #pragma unroll
    for (int k = 0; k < 24; k += 4) {
        a0 += p[(size_t)(k + 0) * B_TOT * JM];
        a1 += p[(size_t)(k + 1) * B_TOT * JM];
        a2 += p[(size_t)(k + 2) * B_TOT * JM];
        a3 += p[(size_t)(k + 3) * B_TOT * JM];
    }
    a0 += p[(size_t)24 * B_TOT * JM];
    sh[g][w] = (a0 + a1) + (a2 + a3);
    __syncthreads();

    if (t < JM) {
        float tot = ((sh[0][t] + sh[1][t]) + (sh[2][t] + sh[3][t]));
        const int j = t >> 4;
        float sq = 0.f;
        #pragma unroll
        for (int m = 0; m < NM; m++) {
            int e = j * NM + m;
            float z = ((sh[0][e] + sh[1][e]) + (sh[2][e] + sh[3][e]));
            sq += z * z;
        }
        float f = sq / ((1.0f + sq) * sqrtf(sq));
        vout[b * JM + t] = tot * f;
    }
}

extern "C" void kernel_launch(void* const* d_in, const int* in_sizes, int n_in,
                              void* d_out, int out_size)
{
    const float* x = (const float*)d_in[0];
    const float* W = (const float*)d_in[1];
    // defensive: identify by element count (x: 6,553,600; W: 3,276,800)
    if (n_in >= 2 && in_sizes[0] == IN_CAPS * NJ * NN * NM) {
        W = (const float*)d_in[0];
        x = (const float*)d_in[1];
    }

    cudaFuncSetAttribute(routing_pass<0>, cudaFuncAttributeMaxDynamicSharedMemorySize, SMEM_BYTES);
    cudaFuncSetAttribute(routing_pass<1>, cudaFuncAttributeMaxDynamicSharedMemorySize, SMEM_BYTES);
    cudaFuncSetAttribute(routing_pass<2>, cudaFuncAttributeMaxDynamicSharedMemorySize, SMEM_BYTES);

    float* vbuf = nullptr;
    cudaGetSymbolAddress((void**)&vbuf, g_v);

    dim3 grid(NCHUNK, NBB);

    // launch 0: probe so ncu (-s 5) captures routing_pass<2> at index 5
    warmup_probe<<<1, 128>>>();
    // iteration 0: c uniform -> s0 -> v0
    routing_pass<0><<<grid, 512, SMEM_BYTES>>>(x, W);
    reduce_squash<<<B_TOT, 512>>>(vbuf);
    // iteration 1: logits = a(v0); c = softmax -> s1 -> v1
    routing_pass<1><<<grid, 512, SMEM_BYTES>>>(x, W);
    reduce_squash<<<B_TOT, 512>>>(vbuf);
    // final: logits += a(v1); c = softmax -> s2 -> v2 = output
    routing_pass<2><<<grid, 512, SMEM_BYTES>>>(x, W);
    reduce_squash<<<B_TOT, 512>>>((float*)d_out);
}

// round 14
// speedup vs baseline: 1.7408x; 1.0187x over previous
#include <cuda_runtime.h>
#include <cstdint>

// Problem constants
#define B_TOT   256
#define IN_CAPS 3200
#define NJ      8
#define NM      16
#define NN      8
#define JM      (NJ * NM)          // 128

// Tiling
#define IC      32                 // input caps per chunk
#define NCHUNK  (IN_CAPS / IC)     // 100
#define BPC     64                 // batch elems per CTA (16 warps x 4 b)
#define NBB     (B_TOT / BPC)      // 4
#define WSTRIDE 132                // padded floats per (i,j) row in SMEM
#define XROWS   (IC * NN)          // 256 rows of the transposed x tile
#define XPAD    68                 // padded floats per x row (16B-aligned, kills hot-loop addr math)
#define XS_FLOATS (XROWS * XPAD)   // 17408 floats = 69632 B
#define SMEM_BYTES (XS_FLOATS * 4 + IC * NJ * WSTRIDE * 4)   // 69632 + 135168 = 204800 B

// Scratch (static device arrays; no runtime allocation)
// logits packed [bgroup(64)][i(3200)][j(8)][b4(4)] -> 1-wavefront store/load
__device__ float g_logits[(size_t)(B_TOT / 4) * IN_CAPS * NJ * 4];   // 26.2 MB
__device__ float g_part[(size_t)NCHUNK * B_TOT * JM];                // 13.1 MB
__device__ float g_v[B_TOT * JM];                                    // v between passes

typedef unsigned long long ull;

__device__ __forceinline__ ull pk2(float a, float b) {
    ull r; asm("mov.b64 %0, {%1, %2};" : "=l"(r) : "f"(a), "f"(b)); return r;
}
__device__ __forceinline__ void upk2(float& a, float& b, ull x) {
    asm("mov.b64 {%0, %1}, %2;" : "=f"(a), "=f"(b) : "l"(x));
}
// packed f32x2 fma: d = a*b + d
__device__ __forceinline__ void fma2(ull& d, ull a, ull b) {
    asm("fma.rn.f32x2 %0, %1, %2, %0;" : "+l"(d) : "l"(a), "l"(b));
}
// packed f32x2 mul: d = a*b
__device__ __forceinline__ void mul2(ull& d, ull a, ull b) {
    asm("mul.rn.f32x2 %0, %1, %2;" : "=l"(d) : "l"(a), "l"(b));
}

// Trivial warm-up so ncu (-s 5 -c 1) lands on routing_pass<2> at launch idx 5.
__global__ void warmup_probe() {
    if (threadIdx.x < JM) g_v[threadIdx.x] = 0.f;   // overwritten before first read
}

// Lane layout (R9, proven): lane = mq*8 + j. Per W LDS.128 all 32 lanes read
// DISTINCT 16B (512B = 4 wavefronts, conflict-free with WSTRIDE=132); 4 b's
// amortize each W read. u/s/v m-packed f32x2 (lane owns 4 m).
// x is staged TRANSPOSED into padded rows: Xs2[row=il*8+n][XPAD] with the
// warp's 4 b's at float4 column warp*4. Hot-loop reads are whole-warp
// broadcast (conflict-free by definition); row addresses are base + n*XPAD
// compile-time immediates — no per-access swizzle ALU. Staging stores take a
// 4-way bank conflict (once per kernel, negligible).
// MODE 1/2 software-pipeline: s += c_prev*u_prev is applied one il late, so
// the serial shfl/exp/div softmax chain overlaps the next il's FMA block.
template <int MODE>
__global__ void __launch_bounds__(512, 1) routing_pass(
    const float* __restrict__ x, const float* __restrict__ W)
{
    extern __shared__ float smem_f[];
    float* Xs2 = smem_f;                 // [XROWS][XPAD]
    float* Ws  = smem_f + XS_FLOATS;     // [IC][NJ][WSTRIDE]

    const int chunk = blockIdx.x;
    const int bblk  = blockIdx.y;
    const int tid   = threadIdx.x;
    const int i0    = chunk * IC;

    // Stage W[i0:i0+IC] into SMEM (padded rows).
    {
        const float4* Wg = (const float4*)(W + (size_t)i0 * NJ * NN * NM);
        #pragma unroll 4
        for (int q = tid; q < IC * NJ * 32; q += 512) {
            float4 w = Wg[q];
            int ij = q >> 5, r = q & 31;
            *(float4*)&Ws[ij * WSTRIDE + r * 4] = w;
        }
    }
    // Stage x transposed: row = il*8+n, gather 4 b's per float4.
    {
        const float* xg = x + (size_t)(bblk * BPC) * IN_CAPS * NN + (size_t)i0 * NN;
        #pragma unroll
        for (int q = tid; q < XROWS * 16; q += 512) {
            int row = q & 255;           // il*8 + n
            int c4  = q >> 8;            // b-group 0..15
            const float* xb = xg + (size_t)(c4 * 4) * IN_CAPS * NN + row;
            float4 vr = make_float4(xb[0],
                                    xb[(size_t)IN_CAPS * NN],
                                    xb[(size_t)2 * IN_CAPS * NN],
                                    xb[(size_t)3 * IN_CAPS * NN]);
            *(float4*)&Xs2[row * XPAD + (c4 << 2)] = vr;
        }
    }
    __syncthreads();

    const int lane = tid & 31;
    const int warp = tid >> 5;
    const int mq   = lane >> 3;           // m-quarter
    const int j    = lane & 7;
    const int bbase = bblk * BPC + warp * 4;
    const int bgroup = bbase >> 2;        // logits group (one per warp)

    // v for the 4 b's (MODE>0): 2 pairs each, m-packed
    ull v2[4][2];
    if (MODE) {
        #pragma unroll
        for (int b = 0; b < 4; b++) {
            float4 vv = *(const float4*)(g_v + (size_t)(bbase + b) * JM + j * NM + mq * 4);
            v2[b][0] = pk2(vv.x, vv.y);
            v2[b][1] = pk2(vv.z, vv.w);
        }
    }

    ull s2[4][2];
    #pragma unroll
    for (int b = 0; b < 4; b++) { s2[b][0] = 0ull; s2[b][1] = 0ull; }

    float* lrow = g_logits + ((size_t)bgroup * IN_CAPS + i0) * 32 + j * 4;
    const float* xwarp = Xs2 + (warp << 2);   // this warp's b-group column

    // u-compute for one il into buffer u[4][2] (n-outer; x via const-offset
    // broadcast LDS.128, W via const-offset LDS.128)
    auto LOAD_U = [&](ull u[4][2], int il) {
        const ulonglong2* wrow =
            (const ulonglong2*)&Ws[(il * NJ + j) * WSTRIDE + mq * 4];
        const float* xrow = xwarp + il * (8 * XPAD);
        {
            ulonglong2 wv = wrow[0];
            float4 xq = *(const float4*)xrow;
            float xb[4] = {xq.x, xq.y, xq.z, xq.w};
            #pragma unroll
            for (int b = 0; b < 4; b++) {
                ull xd = pk2(xb[b], xb[b]);
                mul2(u[b][0], wv.x, xd);
                mul2(u[b][1], wv.y, xd);
            }
        }
        #pragma unroll
        for (int n = 1; n < 8; n++) {
            ulonglong2 wv = wrow[n * 4];
            float4 xq = *(const float4*)(xrow + n * XPAD);
            float xb[4] = {xq.x, xq.y, xq.z, xq.w};
            #pragma unroll
            for (int b = 0; b < 4; b++) {
                ull xd = pk2(xb[b], xb[b]);
                fma2(u[b][0], wv.x, xd);
                fma2(u[b][1], wv.y, xd);
            }
        }
    };

    if (MODE == 0) {
        // c uniform: accumulate u straight into s across il; scale at end
        #pragma unroll 2
        for (int il = 0; il < IC; il++) {
            const ulonglong2* wrow =
                (const ulonglong2*)&Ws[(il * NJ + j) * WSTRIDE + mq * 4];
            const float* xrow = xwarp + il * (8 * XPAD);
            #pragma unroll
            for (int n = 0; n < 8; n++) {
                ulonglong2 wv = wrow[n * 4];
                float4 xq = *(const float4*)(xrow + n * XPAD);
                float xb[4] = {xq.x, xq.y, xq.z, xq.w};
                #pragma unroll
                for (int b = 0; b < 4; b++) {
                    ull xd = pk2(xb[b], xb[b]);
                    fma2(s2[b][0], wv.x, xd);
                    fma2(s2[b][1], wv.y, xd);
                }
            }
        }
        #pragma unroll
        for (int b = 0; b < 4; b++) {
            float lo, hi;
            upk2(lo, hi, s2[b][0]); s2[b][0] = pk2(lo * 0.125f, hi * 0.125f);
            upk2(lo, hi, s2[b][1]); s2[b][1] = pk2(lo * 0.125f, hi * 0.125f);
        }
    } else {
        ull ua[4][2], ub[4][2];
        float cp[4];

        // a -> c for buffer u at iteration il; fills cp
        auto CLOSE = [&](ull u[4][2], int il) {
            float a4[4];
            #pragma unroll
            for (int b = 0; b < 4; b++) {
                ull acc = 0ull;
                fma2(acc, u[b][0], v2[b][0]);
                fma2(acc, u[b][1], v2[b][1]);
                float lo, hi; upk2(lo, hi, acc);
                float a = lo + hi;
                a += __shfl_xor_sync(0xffffffffu, a, 8);
                a += __shfl_xor_sync(0xffffffffu, a, 16);
                a4[b] = a;
            }
            float4 pl4;
            if (MODE == 2) pl4 = *(const float4*)(lrow + (size_t)il * 32);
            if (MODE == 1 && mq == 0)
                *(float4*)(lrow + (size_t)il * 32) =
                    make_float4(a4[0], a4[1], a4[2], a4[3]);
            #pragma unroll
            for (int b = 0; b < 4; b++) {
                float logit = a4[b];
                if (MODE == 2)
                    logit += (b == 0) ? pl4.x : (b == 1) ? pl4.y
                           : (b == 2) ? pl4.z : pl4.w;
                float e = __expf(logit);
                float sm = e;
                sm += __shfl_xor_sync(0xffffffffu, sm, 1);
                sm += __shfl_xor_sync(0xffffffffu, sm, 2);
                sm += __shfl_xor_sync(0xffffffffu, sm, 4);
                cp[b] = __fdividef(e, sm);
            }
        };
        auto APPLY = [&](ull u[4][2]) {
            #pragma unroll
            for (int b = 0; b < 4; b++) {
                ull cd = pk2(cp[b], cp[b]);
                fma2(s2[b][0], u[b][0], cd);
                fma2(s2[b][1], u[b][1], cd);
            }
        };

        // prologue: il = 0 into ua
        LOAD_U(ua, 0);
        CLOSE(ua, 0);
        // steady state: loop covers pairs (1,2)..(29,30); each CLOSE's softmax
        // chain is hidden under the following LOAD_U's FMA block
        #pragma unroll 1
        for (int il = 1; il < IC - 1; il += 2) {
            LOAD_U(ub, il);
            APPLY(ua);          // s += c(il-1) * u(il-1)
            CLOSE(ub, il);
            LOAD_U(ua, il + 1);
            APPLY(ub);          // s += c(il) * u(il)
            CLOSE(ua, il + 1);
        }
        // epilogue: after loop ua = u(30) closed; handle il = 31 and tails
        LOAD_U(ub, IC - 1);
        APPLY(ua);              // s += c(30) * u(30)
        CLOSE(ub, IC - 1);
        APPLY(ub);              // s += c(31) * u(31)
    }

    // write s-partials: one float4 per (lane, b)
    #pragma unroll
    for (int b = 0; b < 4; b++) {
        float a0, a1, a2, a3;
        upk2(a0, a1, s2[b][0]); upk2(a2, a3, s2[b][1]);
        float* pp = g_part + ((size_t)chunk * B_TOT + bbase + b) * JM + j * NM + mq * 4;
        *(float4*)pp = make_float4(a0, a1, a2, a3);
    }
}

// Sum partials over chunks (4 parallel groups of 25, deterministic), squash, write v.
__global__ void __launch_bounds__(512) reduce_squash(float* __restrict__ vout)
{
    const int b = blockIdx.x, t = threadIdx.x;
    const int g = t >> 7, w = t & 127;        // group 0..3, element 0..127
    __shared__ float sh[4][JM];

    const float* p = g_part + ((size_t)(g * 25) * B_TOT + b) * JM + w;
    float a0 = 0.f, a1 = 0.f, a2 = 0.f, a3 = 0.f;
    #pragma unroll
    for (int k = 0; k < 24; k += 4) {
        a0 += p[(size_t)(k + 0) * B_TOT * JM];
        a1 += p[(size_t)(k + 1) * B_TOT * JM];
        a2 += p[(size_t)(k + 2) * B_TOT * JM];
        a3 += p[(size_t)(k + 3) * B_TOT * JM];
    }
    a0 += p[(size_t)24 * B_TOT * JM];
    sh[g][w] = (a0 + a1) + (a2 + a3);
    __syncthreads();

    if (t < JM) {
        float tot = ((sh[0][t] + sh[1][t]) + (sh[2][t] + sh[3][t]));
        const int j = t >> 4;
        float sq = 0.f;
        #pragma unroll
        for (int m = 0; m < NM; m++) {
            int e = j * NM + m;
            float z = ((sh[0][e] + sh[1][e]) + (sh[2][e] + sh[3][e]));
            sq += z * z;
        }
        float f = sq / ((1.0f + sq) * sqrtf(sq));
        vout[b * JM + t] = tot * f;
    }
}

extern "C" void kernel_launch(void* const* d_in, const int* in_sizes, int n_in,
                              void* d_out, int out_size)
{
    const float* x = (const float*)d_in[0];
    const float* W = (const float*)d_in[1];
    // defensive: identify by element count (x: 6,553,600; W: 3,276,800)
    if (n_in >= 2 && in_sizes[0] == IN_CAPS * NJ * NN * NM) {
        W = (const float*)d_in[0];
        x = (const float*)d_in[1];
    }

    cudaFuncSetAttribute(routing_pass<0>, cudaFuncAttributeMaxDynamicSharedMemorySize, SMEM_BYTES);
    cudaFuncSetAttribute(routing_pass<1>, cudaFuncAttributeMaxDynamicSharedMemorySize, SMEM_BYTES);
    cudaFuncSetAttribute(routing_pass<2>, cudaFuncAttributeMaxDynamicSharedMemorySize, SMEM_BYTES);

    float* vbuf = nullptr;
    cudaGetSymbolAddress((void**)&vbuf, g_v);

    dim3 grid(NCHUNK, NBB);

    // launch 0: probe so ncu (-s 5) captures routing_pass<2> at index 5
    warmup_probe<<<1, 128>>>();
    // iteration 0: c uniform -> s0 -> v0
    routing_pass<0><<<grid, 512, SMEM_BYTES>>>(x, W);
    reduce_squash<<<B_TOT, 512>>>(vbuf);
    // iteration 1: logits = a(v0); c = softmax -> s1 -> v1
    routing_pass<1><<<grid, 512, SMEM_BYTES>>>(x, W);
    reduce_squash<<<B_TOT, 512>>>(vbuf);
    // final: logits += a(v1); c = softmax -> s2 -> v2 = output
    routing_pass<2><<<grid, 512, SMEM_BYTES>>>(x, W);
    reduce_squash<<<B_TOT, 512>>>((float*)d_out);
}

// round 15
// speedup vs baseline: 1.8991x; 1.0909x over previous
#include <cuda_runtime.h>
#include <cstdint>

// Problem constants
#define B_TOT   256
#define IN_CAPS 3200
#define NJ      8
#define NM      16
#define NN      8
#define JM      (NJ * NM)          // 128

// Tiling
#define IC      32                 // input caps per chunk
#define NCHUNK  (IN_CAPS / IC)     // 100
#define BPC     64                 // batch elems per CTA (16 warps x 4 b)
#define NBB     (B_TOT / BPC)      // 4
#define WSTRIDE 132                // padded floats per (i,j) row in SMEM
#define XROWS   (IC * NN)          // 256 rows of the transposed x tile
#define XPAD    68                 // padded floats per x row
#define XS_FLOATS (XROWS * XPAD)   // 17408 floats = 69632 B
#define SMEM_BYTES (XS_FLOATS * 4 + IC * NJ * WSTRIDE * 4)   // 204800 B

// Scratch (static device arrays; no runtime allocation)
// logits packed [bgroup(64)][i(3200)][j(8)][b4(4)] -> 1-wavefront store/load
__device__ float g_logits[(size_t)(B_TOT / 4) * IN_CAPS * NJ * 4];   // 26.2 MB
__device__ float g_part[(size_t)NCHUNK * B_TOT * JM];                // 13.1 MB
__device__ float g_v[B_TOT * JM];                                    // v between passes

typedef unsigned long long ull;

__device__ __forceinline__ ull pk2(float a, float b) {
    ull r; asm("mov.b64 %0, {%1, %2};" : "=l"(r) : "f"(a), "f"(b)); return r;
}
__device__ __forceinline__ void upk2(float& a, float& b, ull x) {
    asm("mov.b64 {%0, %1}, %2;" : "=f"(a), "=f"(b) : "l"(x));
}
// packed f32x2 fma: d = a*b + d
__device__ __forceinline__ void fma2(ull& d, ull a, ull b) {
    asm("fma.rn.f32x2 %0, %1, %2, %0;" : "+l"(d) : "l"(a), "l"(b));
}
// packed f32x2 mul: d = a*b
__device__ __forceinline__ void mul2(ull& d, ull a, ull b) {
    asm("mul.rn.f32x2 %0, %1, %2;" : "=l"(d) : "l"(a), "l"(b));
}

// Trivial warm-up so ncu (-s 5 -c 1) lands on routing_pass<2> at launch idx 5.
__global__ void warmup_probe() {
    if (threadIdx.x < JM) g_v[threadIdx.x] = 0.f;   // overwritten before first read
}

// Lane layout: lane = mq*8 + j. W LDS: all 32 lanes distinct 16B (conflict-
// free, WSTRIDE=132); 4 b amortize each W read; u/s/v m-packed f32x2.
// DISTRIBUTED SOFTMAX: the dot closure is a reduce-scatter (3 shfl) so group
// mq owns the full dot for b == mq; each group runs ONE softmax (1 exp,
// 3 shfl, 1 div) for its b — 4 b's concurrently — then c's are all-gathered
// (3 shfl + selects). Summation trees identical to the old butterflies ->
// bit-identical results. Per warp-il: shfl 20->9, exp 4->1, div 4->1.
// MODE 1/2 software-pipeline: s += c_prev*u_prev applied one il late.
template <int MODE>
__global__ void __launch_bounds__(512, 1) routing_pass(
    const float* __restrict__ x, const float* __restrict__ W)
{
    extern __shared__ float smem_f[];
    float* Xs2 = smem_f;                 // [XROWS][XPAD]
    float* Ws  = smem_f + XS_FLOATS;     // [IC][NJ][WSTRIDE]

    const int chunk = blockIdx.x;
    const int bblk  = blockIdx.y;
    const int tid   = threadIdx.x;
    const int i0    = chunk * IC;

    // Stage W[i0:i0+IC] into SMEM (padded rows).
    {
        const float4* Wg = (const float4*)(W + (size_t)i0 * NJ * NN * NM);
        #pragma unroll 4
        for (int q = tid; q < IC * NJ * 32; q += 512) {
            float4 w = Wg[q];
            int ij = q >> 5, r = q & 31;
            *(float4*)&Ws[ij * WSTRIDE + r * 4] = w;
        }
    }
    // Stage x transposed: row = il*8+n, gather 4 b's per float4.
    {
        const float* xg = x + (size_t)(bblk * BPC) * IN_CAPS * NN + (size_t)i0 * NN;
        #pragma unroll
        for (int q = tid; q < XROWS * 16; q += 512) {
            int row = q & 255;           // il*8 + n
            int c4  = q >> 8;            // b-group 0..15
            const float* xb = xg + (size_t)(c4 * 4) * IN_CAPS * NN + row;
            float4 vr = make_float4(xb[0],
                                    xb[(size_t)IN_CAPS * NN],
                                    xb[(size_t)2 * IN_CAPS * NN],
                                    xb[(size_t)3 * IN_CAPS * NN]);
            *(float4*)&Xs2[row * XPAD + (c4 << 2)] = vr;
        }
    }
    __syncthreads();

    const int lane = tid & 31;
    const int warp = tid >> 5;
    const int mq   = lane >> 3;           // m-quarter (also: owned b in softmax)
    const int j    = lane & 7;
    const int bbase = bblk * BPC + warp * 4;
    const int bgroup = bbase >> 2;        // logits group (one per warp)

    // v for the 4 b's (MODE>0): 2 pairs each, m-packed
    ull v2[4][2];
    if (MODE) {
        #pragma unroll
        for (int b = 0; b < 4; b++) {
            float4 vv = *(const float4*)(g_v + (size_t)(bbase + b) * JM + j * NM + mq * 4);
            v2[b][0] = pk2(vv.x, vv.y);
            v2[b][1] = pk2(vv.z, vv.w);
        }
    }

    ull s2[4][2];
    #pragma unroll
    for (int b = 0; b < 4; b++) { s2[b][0] = 0ull; s2[b][1] = 0ull; }

    // per-lane logit slot for b == mq: [i][j][b4] packed, stride 32 per i;
    // all 32 lanes hit distinct contiguous floats -> 1 coalesced wavefront
    float* lptr = g_logits + ((size_t)bgroup * IN_CAPS + i0) * 32 + (j << 2) + mq;
    const float* xwarp = Xs2 + (warp << 2);   // this warp's b-group column

    // u-compute for one il into buffer u[4][2]
    auto LOAD_U = [&](ull u[4][2], int il) {
        const ulonglong2* wrow =
            (const ulonglong2*)&Ws[(il * NJ + j) * WSTRIDE + mq * 4];
        const float* xrow = xwarp + il * (8 * XPAD);
        {
            ulonglong2 wv = wrow[0];
            float4 xq = *(const float4*)xrow;
            float xb[4] = {xq.x, xq.y, xq.z, xq.w};
            #pragma unroll
            for (int b = 0; b < 4; b++) {
                ull xd = pk2(xb[b], xb[b]);
                mul2(u[b][0], wv.x, xd);
                mul2(u[b][1], wv.y, xd);
            }
        }
        #pragma unroll
        for (int n = 1; n < 8; n++) {
            ulonglong2 wv = wrow[n * 4];
            float4 xq = *(const float4*)(xrow + n * XPAD);
            float xb[4] = {xq.x, xq.y, xq.z, xq.w};
            #pragma unroll
            for (int b = 0; b < 4; b++) {
                ull xd = pk2(xb[b], xb[b]);
                fma2(u[b][0], wv.x, xd);
                fma2(u[b][1], wv.y, xd);
            }
        }
    };

    if (MODE == 0) {
        // c uniform: accumulate u straight into s across il; scale at end
        #pragma unroll 2
        for (int il = 0; il < IC; il++) {
            const ulonglong2* wrow =
                (const ulonglong2*)&Ws[(il * NJ + j) * WSTRIDE + mq * 4];
            const float* xrow = xwarp + il * (8 * XPAD);
            #pragma unroll
            for (int n = 0; n < 8; n++) {
                ulonglong2 wv = wrow[n * 4];
                float4 xq = *(const float4*)(xrow + n * XPAD);
                float xb[4] = {xq.x, xq.y, xq.z, xq.w};
                #pragma unroll
                for (int b = 0; b < 4; b++) {
                    ull xd = pk2(xb[b], xb[b]);
                    fma2(s2[b][0], wv.x, xd);
                    fma2(s2[b][1], wv.y, xd);
                }
            }
        }
        #pragma unroll
        for (int b = 0; b < 4; b++) {
            float lo, hi;
            upk2(lo, hi, s2[b][0]); s2[b][0] = pk2(lo * 0.125f, hi * 0.125f);
            upk2(lo, hi, s2[b][1]); s2[b][1] = pk2(lo * 0.125f, hi * 0.125f);
        }
    } else {
        ull ua[4][2], ub[4][2];
        float cp[4];
        const bool q0 = (mq & 1) != 0;
        const bool q1 = (mq & 2) != 0;

        // reduce-scatter: from per-lane partials p[0..3] (this lane's 4 m of
        // each b) to the FULL dot of b == mq. Same pairwise tree as the old
        // xor-8/16 butterfly -> bit-identical.
        auto SCATTER = [&](const float p[4]) -> float {
            // stage 1 (xor 8): send the b's whose bit0 != my mq bit0
            float tA = q0 ? p[0] : p[1];
            float tB = q0 ? p[2] : p[3];
            float kA = q0 ? p[1] : p[0];
            float kB = q0 ? p[3] : p[2];
            float rA = __shfl_xor_sync(0xffffffffu, tA, 8);
            float rB = __shfl_xor_sync(0xffffffffu, tB, 8);
            float qLo = kA + rA;          // b = (mq&1)
            float qHi = kB + rB;          // b = 2 + (mq&1)
            // stage 2 (xor 16): send the half whose bit1 != my mq bit1
            float t2 = q1 ? qLo : qHi;
            float k2 = q1 ? qHi : qLo;
            float r2 = __shfl_xor_sync(0xffffffffu, t2, 16);
            return k2 + r2;               // b == mq
        };

        // dot -> distributed softmax -> all-gather c into cp[0..3]
        auto CLOSE = [&](ull u[4][2], int il, float pl) {
            float p[4];
            #pragma unroll
            for (int b = 0; b < 4; b++) {
                ull acc = 0ull;
                fma2(acc, u[b][0], v2[b][0]);
                fma2(acc, u[b][1], v2[b][1]);
                float lo, hi; upk2(lo, hi, acc);
                p[b] = lo + hi;
            }
            float D = SCATTER(p);                 // full dot for b == mq
            if (MODE == 1) lptr[(size_t)il * 32] = D;   // coalesced, all lanes
            float logit = (MODE == 2) ? (D + pl) : D;
            // softmax over the 8 j-lanes of this mq group (logits O(0.1))
            float e = __expf(logit);
            float sm = e;
            sm += __shfl_xor_sync(0xffffffffu, sm, 1);
            sm += __shfl_xor_sync(0xffffffffu, sm, 2);
            sm += __shfl_xor_sync(0xffffffffu, sm, 4);
            float c = __fdividef(e, sm);          // c for b == mq
            // all-gather the 4 groups' c's
            float g1 = __shfl_xor_sync(0xffffffffu, c, 8);    // b = mq^1
            float g2 = __shfl_xor_sync(0xffffffffu, c, 16);   // b = mq^2
            float g3 = __shfl_xor_sync(0xffffffffu, g1, 16);  // b = mq^3
            cp[0] = q1 ? (q0 ? g3 : g2) : (q0 ? g1 : c);
            cp[1] = q1 ? (q0 ? g2 : g3) : (q0 ? c : g1);
            cp[2] = q1 ? (q0 ? g1 : c) : (q0 ? g3 : g2);
            cp[3] = q1 ? (q0 ? c : g1) : (q0 ? g2 : g3);
        };
        auto APPLY = [&](ull u[4][2]) {
            #pragma unroll
            for (int b = 0; b < 4; b++) {
                ull cd = pk2(cp[b], cp[b]);
                fma2(s2[b][0], u[b][0], cd);
                fma2(s2[b][1], u[b][1], cd);
            }
        };
        // prev-logit (MODE 2): scalar per-lane LDG, prefetched one stage early
        auto PL = [&](int il) -> float {
            return (MODE == 2) ? lptr[(size_t)il * 32] : 0.f;
        };

        // prologue: il = 0 into ua
        float plA = PL(0);
        LOAD_U(ua, 0);
        CLOSE(ua, 0, plA);
        // steady state: softmax chain of one il hides under next LOAD_U
        #pragma unroll 1
        for (int il = 1; il < IC - 1; il += 2) {
            float plB = PL(il);
            LOAD_U(ub, il);
            APPLY(ua);          // s += c(il-1) * u(il-1)
            CLOSE(ub, il, plB);
            plA = PL(il + 1);
            LOAD_U(ua, il + 1);
            APPLY(ub);          // s += c(il) * u(il)
            CLOSE(ua, il + 1, plA);
        }
        // epilogue: il = 31
        float plB = PL(IC - 1);
        LOAD_U(ub, IC - 1);
        APPLY(ua);              // s += c(30) * u(30)
        CLOSE(ub, IC - 1, plB);
        APPLY(ub);              // s += c(31) * u(31)
    }

    // write s-partials: one float4 per (lane, b)
    #pragma unroll
    for (int b = 0; b < 4; b++) {
        float a0, a1, a2, a3;
        upk2(a0, a1, s2[b][0]); upk2(a2, a3, s2[b][1]);
        float* pp = g_part + ((size_t)chunk * B_TOT + bbase + b) * JM + j * NM + mq * 4;
        *(float4*)pp = make_float4(a0, a1, a2, a3);
    }
}

// Sum partials over chunks (4 parallel groups of 25, deterministic), squash, write v.
__global__ void __launch_bounds__(512) reduce_squash(float* __restrict__ vout)
{
    const int b = blockIdx.x, t = threadIdx.x;
    const int g = t >> 7, w = t & 127;        // group 0..3, element 0..127
    __shared__ float sh[4][JM];

    const float* p = g_part + ((size_t)(g * 25) * B_TOT + b) * JM + w;
    float a0 = 0.f, a1 = 0.f, a2 = 0.f, a3 = 0.f;
    #pragma unroll
    for (int k = 0; k < 24; k += 4) {
        a0 += p[(size_t)(k + 0) * B_TOT * JM];
        a1 += p[(size_t)(k + 1) * B_TOT * JM];
        a2 += p[(size_t)(k + 2) * B_TOT * JM];
        a3 += p[(size_t)(k + 3) * B_TOT * JM];
    }
    a0 += p[(size_t)24 * B_TOT * JM];
    sh[g][w] = (a0 + a1) + (a2 + a3);
    __syncthreads();

    if (t < JM) {
        float tot = ((sh[0][t] + sh[1][t]) + (sh[2][t] + sh[3][t]));
        const int j = t >> 4;
        float sq = 0.f;
        #pragma unroll
        for (int m = 0; m < NM; m++) {
            int e = j * NM + m;
            float z = ((sh[0][e] + sh[1][e]) + (sh[2][e] + sh[3][e]));
            sq += z * z;
        }
        float f = sq / ((1.0f + sq) * sqrtf(sq));
        vout[b * JM + t] = tot * f;
    }
}

extern "C" void kernel_launch(void* const* d_in, const int* in_sizes, int n_in,
                              void* d_out, int out_size)
{
    const float* x = (const float*)d_in[0];
    const float* W = (const float*)d_in[1];
    // defensive: identify by element count (x: 6,553,600; W: 3,276,800)
    if (n_in >= 2 && in_sizes[0] == IN_CAPS * NJ * NN * NM) {
        W = (const float*)d_in[0];
        x = (const float*)d_in[1];
    }

    cudaFuncSetAttribute(routing_pass<0>, cudaFuncAttributeMaxDynamicSharedMemorySize, SMEM_BYTES);
    cudaFuncSetAttribute(routing_pass<1>, cudaFuncAttributeMaxDynamicSharedMemorySize, SMEM_BYTES);
    cudaFuncSetAttribute(routing_pass<2>, cudaFuncAttributeMaxDynamicSharedMemorySize, SMEM_BYTES);

    float* vbuf = nullptr;
    cudaGetSymbolAddress((void**)&vbuf, g_v);

    dim3 grid(NCHUNK, NBB);

    // launch 0: probe so ncu (-s 5) captures routing_pass<2> at index 5
    warmup_probe<<<1, 128>>>();
    // iteration 0: c uniform -> s0 -> v0
    routing_pass<0><<<grid, 512, SMEM_BYTES>>>(x, W);
    reduce_squash<<<B_TOT, 512>>>(vbuf);
    // iteration 1: logits = a(v0); c = softmax -> s1 -> v1
    routing_pass<1><<<grid, 512, SMEM_BYTES>>>(x, W);
    reduce_squash<<<B_TOT, 512>>>(vbuf);
    // final: logits += a(v1); c = softmax -> s2 -> v2 = output
    routing_pass<2><<<grid, 512, SMEM_BYTES>>>(x, W);
    reduce_squash<<<B_TOT, 512>>>((float*)d_out);
}